// round 1
// baseline (speedup 1.0000x reference)
#include <cuda_runtime.h>
#include <math.h>

// Problem constants
#define BSZ   4
#define TLEN  2048
#define CDIM  1024
#define NHEAD 16
#define HDIM  64
#define MTOT  (BSZ * TLEN)          // 8192

// Scratch (device globals — no allocation allowed)
__device__ float g_q[BSZ * NHEAD * TLEN * HDIM];   // [b,h,t,d]
__device__ float g_k[BSZ * NHEAD * TLEN * HDIM];
__device__ float g_v[BSZ * NHEAD * TLEN * HDIM];
__device__ float g_att[BSZ * TLEN * CDIM];         // [b,t,c] attention output

// ---------------------------------------------------------------------------
// 128x128x8 SGEMM, 256 threads, 8x8 per-thread micro-tile.
// MODE 0: A = x [8192,1024], B = W_attn [1024,3072]; epilogue adds b_attn and
//         per-head bQ/bK/bV and scatters into g_q/g_k/g_v with [b,h,t,d] layout.
// MODE 1: A = g_att [8192,1024], B = W_proj [1024,1024]; epilogue adds b_proj,
//         writes Cout.
// ---------------------------------------------------------------------------
template <int MODE>
__global__ __launch_bounds__(256)
void sgemm128(const float* __restrict__ A,
              const float* __restrict__ Bw,
              const float* __restrict__ bias,
              const float* __restrict__ bQ,
              const float* __restrict__ bK,
              const float* __restrict__ bV,
              float* __restrict__ Cout,
              int K, int N)
{
    __shared__ float As[8][128];   // transposed A tile: As[k][m]
    __shared__ float Bs[8][128];   // Bs[k][n]

    const int tid = threadIdx.x;
    const int m0  = blockIdx.y * 128;
    const int n0  = blockIdx.x * 128;

    const int arow = tid >> 1;            // 0..127
    const int acol = (tid & 1) * 4;       // 0 or 4
    const int brow = tid >> 5;            // 0..7
    const int bcol = (tid & 31) * 4;      // 0..124

    const int ty = tid >> 4;              // 0..15 -> m group
    const int tx = tid & 15;              // 0..15 -> n group

    const float* Ap = (MODE == 1) ? (const float*)g_att : A;

    float acc[8][8];
#pragma unroll
    for (int i = 0; i < 8; i++)
#pragma unroll
        for (int j = 0; j < 8; j++) acc[i][j] = 0.0f;

    const float* aptr = Ap + (m0 + arow) * K + acol;
    const float* bptr = Bw + brow * N + n0 + bcol;

    for (int k0 = 0; k0 < K; k0 += 8) {
        float4 av = *(const float4*)(aptr + k0);
        float4 bv = *(const float4*)(bptr + k0 * N);

        __syncthreads();
        As[acol + 0][arow] = av.x;
        As[acol + 1][arow] = av.y;
        As[acol + 2][arow] = av.z;
        As[acol + 3][arow] = av.w;
        *(float4*)&Bs[brow][bcol] = bv;
        __syncthreads();

#pragma unroll
        for (int kk = 0; kk < 8; kk++) {
            float a[8], b[8];
            *(float4*)&a[0] = *(const float4*)&As[kk][ty * 8];
            *(float4*)&a[4] = *(const float4*)&As[kk][ty * 8 + 4];
            *(float4*)&b[0] = *(const float4*)&Bs[kk][tx * 8];
            *(float4*)&b[4] = *(const float4*)&Bs[kk][tx * 8 + 4];
#pragma unroll
            for (int i = 0; i < 8; i++)
#pragma unroll
                for (int j = 0; j < 8; j++)
                    acc[i][j] += a[i] * b[j];
        }
    }

    // Epilogue
    const int nbase = n0 + tx * 8;   // 8 consecutive columns, never crossing a
                                     // 64-boundary (multiples of 8), and the
                                     // whole 128-wide block is inside one of
                                     // the q/k/v sections (1024 % 128 == 0).
#pragma unroll
    for (int i = 0; i < 8; i++) {
        const int m = m0 + ty * 8 + i;
        float out[8];
#pragma unroll
        for (int j = 0; j < 8; j++) out[j] = acc[i][j] + bias[nbase + j];

        if (MODE == 1) {
            float* dst = Cout + m * N + nbase;
            *(float4*)dst       = make_float4(out[0], out[1], out[2], out[3]);
            *(float4*)(dst + 4) = make_float4(out[4], out[5], out[6], out[7]);
        } else {
            const int b = m >> 11;         // / TLEN
            const int t = m & (TLEN - 1);
            float* dst;
            if (nbase < CDIM) {
                const int n2 = nbase;
#pragma unroll
                for (int j = 0; j < 8; j++) out[j] += bQ[n2 + j];
                const int h = n2 >> 6, dd = n2 & 63;
                dst = &g_q[(((b * NHEAD + h) * TLEN) + t) * HDIM + dd];
            } else if (nbase < 2 * CDIM) {
                const int n2 = nbase - CDIM;
#pragma unroll
                for (int j = 0; j < 8; j++) out[j] += bK[n2 + j];
                const int h = n2 >> 6, dd = n2 & 63;
                dst = &g_k[(((b * NHEAD + h) * TLEN) + t) * HDIM + dd];
            } else {
                const int n2 = nbase - 2 * CDIM;
#pragma unroll
                for (int j = 0; j < 8; j++) out[j] += bV[n2 + j];
                const int h = n2 >> 6, dd = n2 & 63;
                dst = &g_v[(((b * NHEAD + h) * TLEN) + t) * HDIM + dd];
            }
            *(float4*)dst       = make_float4(out[0], out[1], out[2], out[3]);
            *(float4*)(dst + 4) = make_float4(out[4], out[5], out[6], out[7]);
        }
    }
}

// ---------------------------------------------------------------------------
// Flash attention (causal). One CTA = one (b,h) pair + 64 query rows.
// 64 threads; each thread owns one full query row (q + 64-wide accumulator in
// registers). K/V tiles of 64x64 in SMEM; S stored transposed (S[j][r]) so
// every SMEM access is broadcast or stride-1 (conflict-free, no padding).
// ---------------------------------------------------------------------------
__global__ __launch_bounds__(64)
void flash_attn()
{
    __shared__ float Ks[64 * 64];
    __shared__ float Vs[64 * 64];
    __shared__ float Ss[64 * 64];   // transposed: Ss[j*64 + r]

    const int r  = threadIdx.x;       // query row within tile
    const int qt = blockIdx.x;        // 0..31
    const int h  = blockIdx.y;
    const int b  = blockIdx.z;

    const int bh = b * NHEAD + h;
    const int qrow = qt * 64 + r;

    // q row in registers, pre-scaled by 1/sqrt(d) = 0.125
    float q[64];
    {
        const float4* qp = (const float4*)(g_q + (bh * TLEN + qrow) * HDIM);
#pragma unroll
        for (int c = 0; c < 16; c++) {
            float4 v = qp[c];
            q[4*c+0] = v.x * 0.125f;
            q[4*c+1] = v.y * 0.125f;
            q[4*c+2] = v.z * 0.125f;
            q[4*c+3] = v.w * 0.125f;
        }
    }

    float acc[64];
#pragma unroll
    for (int d = 0; d < 64; d++) acc[d] = 0.0f;
    float mrow = -1e30f;
    float lrow = 0.0f;

    for (int kt = 0; kt <= qt; kt++) {
        __syncthreads();   // previous iteration done reading Ks/Vs/Ss
        {
            const float4* kg = (const float4*)(g_k + (bh * TLEN + kt * 64) * HDIM);
            const float4* vg = (const float4*)(g_v + (bh * TLEN + kt * 64) * HDIM);
            float4* ks4 = (float4*)Ks;
            float4* vs4 = (float4*)Vs;
#pragma unroll
            for (int i = 0; i < 16; i++) {
                ks4[r + 64 * i] = kg[r + 64 * i];
                vs4[r + 64 * i] = vg[r + 64 * i];
            }
        }
        __syncthreads();

        const bool diag = (kt == qt);
        float tmax = -1e30f;
        for (int j = 0; j < 64; j++) {
            const float4* kr = (const float4*)(Ks + j * 64);
            float s0 = 0.f, s1 = 0.f, s2 = 0.f, s3 = 0.f;
#pragma unroll
            for (int c = 0; c < 16; c++) {
                float4 kv = kr[c];
                s0 += q[4*c+0] * kv.x;
                s1 += q[4*c+1] * kv.y;
                s2 += q[4*c+2] * kv.z;
                s3 += q[4*c+3] * kv.w;
            }
            float s = (s0 + s1) + (s2 + s3);
            if (diag && j > r) s = -1e30f;
            Ss[j * 64 + r] = s;
            tmax = fmaxf(tmax, s);
        }

        const float mnew = fmaxf(mrow, tmax);
        const float corr = __expf(mrow - mnew);
        lrow *= corr;
#pragma unroll
        for (int d = 0; d < 64; d++) acc[d] *= corr;

        for (int j = 0; j < 64; j++) {
            const float p = __expf(Ss[j * 64 + r] - mnew);
            lrow += p;
            const float4* vr = (const float4*)(Vs + j * 64);
#pragma unroll
            for (int c = 0; c < 16; c++) {
                float4 vv = vr[c];
                acc[4*c+0] += p * vv.x;
                acc[4*c+1] += p * vv.y;
                acc[4*c+2] += p * vv.z;
                acc[4*c+3] += p * vv.w;
            }
        }
        mrow = mnew;
    }

    const float inv = 1.0f / lrow;
    float4* op = (float4*)(g_att + (b * TLEN + qrow) * CDIM + h * HDIM);
#pragma unroll
    for (int c = 0; c < 16; c++) {
        op[c] = make_float4(acc[4*c+0] * inv, acc[4*c+1] * inv,
                            acc[4*c+2] * inv, acc[4*c+3] * inv);
    }
}

// ---------------------------------------------------------------------------
// kernel_launch
// Inputs: 0:x 1:W_attn 2:b_attn 3:W_proj 4:b_proj 5:bQ 6:bK 7:bV
// ---------------------------------------------------------------------------
extern "C" void kernel_launch(void* const* d_in, const int* in_sizes, int n_in,
                              void* d_out, int out_size)
{
    const float* x      = (const float*)d_in[0];
    const float* W_attn = (const float*)d_in[1];
    const float* b_attn = (const float*)d_in[2];
    const float* W_proj = (const float*)d_in[3];
    const float* b_proj = (const float*)d_in[4];
    const float* bQ     = (const float*)d_in[5];
    const float* bK     = (const float*)d_in[6];
    const float* bV     = (const float*)d_in[7];
    float* out = (float*)d_out;

    // 1) QKV GEMM + bias + head scatter: [8192,1024] @ [1024,3072]
    {
        dim3 grid(3 * CDIM / 128, MTOT / 128);   // (24, 64)
        sgemm128<0><<<grid, 256>>>(x, W_attn, b_attn, bQ, bK, bV, nullptr,
                                   CDIM, 3 * CDIM);
    }

    // 2) Causal flash attention
    {
        dim3 grid(TLEN / 64, NHEAD, BSZ);        // (32, 16, 4)
        flash_attn<<<grid, 64>>>();
    }

    // 3) Projection GEMM: [8192,1024] @ [1024,1024] + b_proj
    {
        dim3 grid(CDIM / 128, MTOT / 128);       // (8, 64)
        sgemm128<1><<<grid, 256>>>(nullptr, W_proj, b_proj, nullptr, nullptr,
                                   nullptr, out, CDIM, CDIM);
    }
}

// round 4
// speedup vs baseline: 1.5520x; 1.5520x over previous
#include <cuda_runtime.h>
#include <cstdint>
#include <math.h>

// Problem constants
#define BSZ   4
#define TLEN  2048
#define CDIM  1024
#define NHEAD 16
#define HDIM  64
#define MTOT  (BSZ * TLEN)          // 8192

// ---------------------------------------------------------------------------
// Scratch (device globals — no allocation allowed)
// ---------------------------------------------------------------------------
__device__ float g_q[BSZ * NHEAD * TLEN * HDIM];   // [b,h,t,d]
__device__ float g_k[BSZ * NHEAD * TLEN * HDIM];
__device__ float g_v[BSZ * NHEAD * TLEN * HDIM];
__device__ float g_att[BSZ * TLEN * CDIM];         // [b,t,c]
__device__ float g_wT[4 * CDIM * CDIM];            // W_attn^T then W_proj^T

#define WT_PROJ_OFF (3 * CDIM * CDIM)

// ---------------------------------------------------------------------------
// Portable PTX helpers (sm_80+ only; NO tcgen05 — harness targets sm_100)
// ---------------------------------------------------------------------------
__device__ __forceinline__ uint32_t smem_u32(const void* p) {
    uint32_t a;
    asm("{ .reg .u64 t; cvta.to.shared.u64 t, %1; cvt.u32.u64 %0, t; }" : "=r"(a) : "l"(p));
    return a;
}

#define CP_ASYNC16(dst, src) \
    asm volatile("cp.async.cg.shared.global [%0], [%1], 16;" :: "r"(dst), "l"(src))
#define CP_COMMIT() asm volatile("cp.async.commit_group;")
#define CP_WAIT(n)  asm volatile("cp.async.wait_group %0;" :: "n"(n))

__device__ __forceinline__ uint32_t swz(uint32_t off) { return off ^ ((off >> 3) & 0x70); }

__device__ __forceinline__ uint32_t f2tf32(float f) {
    uint32_t r;
    asm("cvt.rna.tf32.f32 %0, %1;" : "=r"(r) : "f"(f));
    return r;
}

// m16n8k8 tf32 mma, fp32 accumulate (sm_80+)
__device__ __forceinline__ void mma_tf32(float c[4],
                                         uint32_t a0, uint32_t a1, uint32_t a2, uint32_t a3,
                                         uint32_t b0, uint32_t b1) {
    asm volatile(
        "mma.sync.aligned.m16n8k8.row.col.f32.tf32.tf32.f32 "
        "{%0,%1,%2,%3}, {%4,%5,%6,%7}, {%8,%9}, {%0,%1,%2,%3};"
        : "+f"(c[0]), "+f"(c[1]), "+f"(c[2]), "+f"(c[3])
        : "r"(a0), "r"(a1), "r"(a2), "r"(a3), "r"(b0), "r"(b1));
}

// ---------------------------------------------------------------------------
// Weight transpose: out[c][r] = in[r][c], written into g_wT + dst_off
// ---------------------------------------------------------------------------
__global__ __launch_bounds__(256)
void transpose_k(const float* __restrict__ in, int dst_off, int R, int C)
{
    __shared__ float t[32][33];
    const int c0 = blockIdx.x * 32, r0 = blockIdx.y * 32;
    const int tx = threadIdx.x, ty = threadIdx.y;
#pragma unroll
    for (int i = ty; i < 32; i += 8)
        t[i][tx] = in[(r0 + i) * C + c0 + tx];
    __syncthreads();
#pragma unroll
    for (int i = ty; i < 32; i += 8)
        g_wT[dst_off + (c0 + i) * R + r0 + tx] = t[tx][i];
}

// ---------------------------------------------------------------------------
// tf32 mma.sync GEMM: C[128,128] per CTA, K=1024, TK=32/stage, 3-stage cp.async.
// 8 warps as 4(M) x 2(N); warp tile 32x64; per warp 2x8 m16n8k8 tiles.
// A smem [128m][32k], B smem [128n][32k], both K-major with 16B-chunk swizzle:
//   elem(r, c) at r*32 + (c ^ ((r&7)<<2)).
// MODE 0: A=x, B=W_attn^T; epilogue adds b_attn + bQ/bK/bV, scatters to q/k/v.
// MODE 1: A=g_att, B=W_proj^T; epilogue adds b_proj, writes Cout.
// ---------------------------------------------------------------------------
#define TK          32
#define STAGES      3
#define STAGE_BYTES 32768                     // A 16KB + B 16KB
#define STAGE_F     8192                      // floats per stage
#define SMEM_GEMM   (STAGES * STAGE_BYTES)    // 98304

template <int MODE>
__device__ __forceinline__ void load_stage(const float* Ap, const float* Bt,
                                           uint32_t sb, int m0, int n0, int tid,
                                           int s, int k0)
{
    const uint32_t base = sb + s * STAGE_BYTES;
#pragma unroll
    for (int j = 0; j < 4; j++) {
        const int idx = tid + j * 256;
        const int r = idx >> 3, c = idx & 7;
        CP_ASYNC16(base + swz(r * 128 + c * 16), Ap + (m0 + r) * CDIM + k0 + c * 4);
    }
#pragma unroll
    for (int j = 0; j < 4; j++) {
        const int idx = tid + j * 256;
        const int r = idx >> 3, c = idx & 7;
        CP_ASYNC16(base + 16384 + swz(r * 128 + c * 16), Bt + (n0 + r) * CDIM + k0 + c * 4);
    }
}

template <int MODE>
__global__ __launch_bounds__(256, 2)
void tc_gemm(const float* __restrict__ A,
             int bt_off,
             const float* __restrict__ bias,
             const float* __restrict__ bQ,
             const float* __restrict__ bK,
             const float* __restrict__ bV,
             float* __restrict__ Cout)
{
    extern __shared__ float smemf[];
    const uint32_t sb = smem_u32(smemf);
    const int tid  = threadIdx.x;
    const int lane = tid & 31;
    const int wid  = tid >> 5;
    const int gid  = lane >> 2;        // 0..7
    const int tig  = lane & 3;         // 0..3
    const int wm   = (wid & 3) * 32;   // warp M offset within CTA
    const int wn   = (wid >> 2) * 64;  // warp N offset within CTA

    const int m0 = blockIdx.y * 128;
    const int n0 = blockIdx.x * 128;

    const float* Ap = (MODE == 1) ? (const float*)g_att : A;
    const float* Bt = g_wT + bt_off;

    float acc[2][8][4];
#pragma unroll
    for (int mt = 0; mt < 2; mt++)
#pragma unroll
        for (int nt = 0; nt < 8; nt++)
#pragma unroll
            for (int j = 0; j < 4; j++) acc[mt][nt][j] = 0.0f;

    // Prologue: stages 0, 1
    load_stage<MODE>(Ap, Bt, sb, m0, n0, tid, 0, 0);
    CP_COMMIT();
    load_stage<MODE>(Ap, Bt, sb, m0, n0, tid, 1, TK);
    CP_COMMIT();

    const int NIT = CDIM / TK;   // 32
    const int xr  = gid << 2;    // swizzle XOR term (r&7 == gid for all our rows)

    int slot = 0;
    for (int i = 0; i < NIT; i++) {
        CP_WAIT(1);
        __syncthreads();

        if (i + 2 < NIT)
            load_stage<MODE>(Ap, Bt, sb, m0, n0, tid, (i + 2) % STAGES, (i + 2) * TK);
        CP_COMMIT();

        const float* As = smemf + slot * STAGE_F;
        const float* Bs = As + 4096;

#pragma unroll
        for (int ks = 0; ks < 4; ks++) {
            const int c0 = ((ks * 8) + tig) ^ xr;
            const int c4 = c0 ^ 4;

            uint32_t a[2][4];
#pragma unroll
            for (int mt = 0; mt < 2; mt++) {
                const int r0 = wm + mt * 16 + gid;
                const int r1 = r0 + 8;
                a[mt][0] = f2tf32(As[r0 * 32 + c0]);
                a[mt][1] = f2tf32(As[r1 * 32 + c0]);
                a[mt][2] = f2tf32(As[r0 * 32 + c4]);
                a[mt][3] = f2tf32(As[r1 * 32 + c4]);
            }
#pragma unroll
            for (int nt = 0; nt < 8; nt++) {
                const int n = wn + nt * 8 + gid;
                const uint32_t b0 = f2tf32(Bs[n * 32 + c0]);
                const uint32_t b1 = f2tf32(Bs[n * 32 + c4]);
                mma_tf32(acc[0][nt], a[0][0], a[0][1], a[0][2], a[0][3], b0, b1);
                mma_tf32(acc[1][nt], a[1][0], a[1][1], a[1][2], a[1][3], b0, b1);
            }
        }
        slot = (slot + 1) % STAGES;
    }

    // Epilogue: thread holds rows {gid, gid+8} cols {tig*2, tig*2+1} per tile.
#pragma unroll
    for (int mt = 0; mt < 2; mt++) {
#pragma unroll
        for (int half = 0; half < 2; half++) {
            const int row = m0 + wm + mt * 16 + gid + half * 8;
#pragma unroll
            for (int nt = 0; nt < 8; nt++) {
                const int col = n0 + wn + nt * 8 + tig * 2;
                float v0 = acc[mt][nt][half * 2 + 0] + bias[col];
                float v1 = acc[mt][nt][half * 2 + 1] + bias[col + 1];

                if (MODE == 1) {
                    *(float2*)&Cout[(size_t)row * CDIM + col] = make_float2(v0, v1);
                } else {
                    const int sec = col >> 10;          // 0=q,1=k,2=v
                    const int n2  = col & 1023;
                    const float* hb = (sec == 0) ? bQ : (sec == 1) ? bK : bV;
                    v0 += hb[n2];
                    v1 += hb[n2 + 1];
                    const int h  = n2 >> 6, dd = n2 & 63;
                    const int b_ = row >> 11, t = row & (TLEN - 1);
                    float* base = (sec == 0) ? g_q : (sec == 1) ? g_k : g_v;
                    *(float2*)&base[(((size_t)(b_ * NHEAD + h) * TLEN) + t) * HDIM + dd] =
                        make_float2(v0, v1);
                }
            }
        }
    }
}

// ---------------------------------------------------------------------------
// Flash attention (causal, fp32 scalar) — unchanged from R1 (passing).
// ---------------------------------------------------------------------------
__global__ __launch_bounds__(64)
void flash_attn()
{
    __shared__ float Ks[64 * 64];
    __shared__ float Vs[64 * 64];
    __shared__ float Ss[64 * 64];   // transposed: Ss[j*64 + r]

    const int r  = threadIdx.x;
    const int qt = blockIdx.x;
    const int h  = blockIdx.y;
    const int b  = blockIdx.z;

    const int bh = b * NHEAD + h;
    const int qrow = qt * 64 + r;

    float q[64];
    {
        const float4* qp = (const float4*)(g_q + (bh * TLEN + qrow) * HDIM);
#pragma unroll
        for (int c = 0; c < 16; c++) {
            float4 v = qp[c];
            q[4*c+0] = v.x * 0.125f;
            q[4*c+1] = v.y * 0.125f;
            q[4*c+2] = v.z * 0.125f;
            q[4*c+3] = v.w * 0.125f;
        }
    }

    float acc[64];
#pragma unroll
    for (int d = 0; d < 64; d++) acc[d] = 0.0f;
    float mrow = -1e30f;
    float lrow = 0.0f;

    for (int kt = 0; kt <= qt; kt++) {
        __syncthreads();
        {
            const float4* kg = (const float4*)(g_k + (bh * TLEN + kt * 64) * HDIM);
            const float4* vg = (const float4*)(g_v + (bh * TLEN + kt * 64) * HDIM);
            float4* ks4 = (float4*)Ks;
            float4* vs4 = (float4*)Vs;
#pragma unroll
            for (int i = 0; i < 16; i++) {
                ks4[r + 64 * i] = kg[r + 64 * i];
                vs4[r + 64 * i] = vg[r + 64 * i];
            }
        }
        __syncthreads();

        const bool diag = (kt == qt);
        float tmax = -1e30f;
        for (int j = 0; j < 64; j++) {
            const float4* kr = (const float4*)(Ks + j * 64);
            float s0 = 0.f, s1 = 0.f, s2 = 0.f, s3 = 0.f;
#pragma unroll
            for (int c = 0; c < 16; c++) {
                float4 kv = kr[c];
                s0 += q[4*c+0] * kv.x;
                s1 += q[4*c+1] * kv.y;
                s2 += q[4*c+2] * kv.z;
                s3 += q[4*c+3] * kv.w;
            }
            float s = (s0 + s1) + (s2 + s3);
            if (diag && j > r) s = -1e30f;
            Ss[j * 64 + r] = s;
            tmax = fmaxf(tmax, s);
        }

        const float mnew = fmaxf(mrow, tmax);
        const float corr = __expf(mrow - mnew);
        lrow *= corr;
#pragma unroll
        for (int d = 0; d < 64; d++) acc[d] *= corr;

        for (int j = 0; j < 64; j++) {
            const float p = __expf(Ss[j * 64 + r] - mnew);
            lrow += p;
            const float4* vr = (const float4*)(Vs + j * 64);
#pragma unroll
            for (int c = 0; c < 16; c++) {
                float4 vv = vr[c];
                acc[4*c+0] += p * vv.x;
                acc[4*c+1] += p * vv.y;
                acc[4*c+2] += p * vv.z;
                acc[4*c+3] += p * vv.w;
            }
        }
        mrow = mnew;
    }

    const float inv = 1.0f / lrow;
    float4* op = (float4*)(g_att + (b * TLEN + qrow) * CDIM + h * HDIM);
#pragma unroll
    for (int c = 0; c < 16; c++) {
        op[c] = make_float4(acc[4*c+0] * inv, acc[4*c+1] * inv,
                            acc[4*c+2] * inv, acc[4*c+3] * inv);
    }
}

// ---------------------------------------------------------------------------
// kernel_launch
// Inputs: 0:x 1:W_attn 2:b_attn 3:W_proj 4:b_proj 5:bQ 6:bK 7:bV
// ---------------------------------------------------------------------------
extern "C" void kernel_launch(void* const* d_in, const int* in_sizes, int n_in,
                              void* d_out, int out_size)
{
    const float* x      = (const float*)d_in[0];
    const float* W_attn = (const float*)d_in[1];
    const float* b_attn = (const float*)d_in[2];
    const float* W_proj = (const float*)d_in[3];
    const float* b_proj = (const float*)d_in[4];
    const float* bQ     = (const float*)d_in[5];
    const float* bK     = (const float*)d_in[6];
    const float* bV     = (const float*)d_in[7];
    float* out = (float*)d_out;

    cudaFuncSetAttribute(tc_gemm<0>, cudaFuncAttributeMaxDynamicSharedMemorySize, SMEM_GEMM);
    cudaFuncSetAttribute(tc_gemm<1>, cudaFuncAttributeMaxDynamicSharedMemorySize, SMEM_GEMM);

    // 0) Transpose weights into K-major form
    {
        dim3 tb(32, 8);
        transpose_k<<<dim3(3 * CDIM / 32, CDIM / 32), tb>>>(W_attn, 0, CDIM, 3 * CDIM);
        transpose_k<<<dim3(CDIM / 32, CDIM / 32), tb>>>(W_proj, WT_PROJ_OFF, CDIM, CDIM);
    }

    // 1) QKV GEMM (tf32 mma.sync) + bias + head scatter
    {
        dim3 grid(3 * CDIM / 128, MTOT / 128);   // (24, 64)
        tc_gemm<0><<<grid, 256, SMEM_GEMM>>>(x, 0, b_attn, bQ, bK, bV, nullptr);
    }

    // 2) Causal flash attention
    {
        dim3 grid(TLEN / 64, NHEAD, BSZ);        // (32, 16, 4)
        flash_attn<<<grid, 64>>>();
    }

    // 3) Projection GEMM (tf32 mma.sync) + b_proj
    {
        dim3 grid(CDIM / 128, MTOT / 128);       // (8, 64)
        tc_gemm<1><<<grid, 256, SMEM_GEMM>>>(nullptr, WT_PROJ_OFF, b_proj,
                                             nullptr, nullptr, nullptr, out);
    }
}

// round 7
// speedup vs baseline: 2.4934x; 1.6066x over previous
#include <cuda_runtime.h>
#include <cstdint>
#include <math.h>

// Problem constants
#define BSZ   4
#define TLEN  2048
#define CDIM  1024
#define NHEAD 16
#define HDIM  64
#define MTOT  (BSZ * TLEN)          // 8192

// ---------------------------------------------------------------------------
// Scratch (device globals — no allocation allowed)
// ---------------------------------------------------------------------------
__device__ float g_q[BSZ * NHEAD * TLEN * HDIM];   // [b,h,t,d]
__device__ float g_k[BSZ * NHEAD * TLEN * HDIM];
__device__ float g_v[BSZ * NHEAD * TLEN * HDIM];
__device__ float g_att[BSZ * TLEN * CDIM];         // [b,t,c]
__device__ float g_wT[4 * CDIM * CDIM];            // W_attn^T then W_proj^T

#define WT_PROJ_OFF (3 * CDIM * CDIM)

// ---------------------------------------------------------------------------
// Portable PTX helpers (sm_80+ only; harness targets plain sm_100)
// ---------------------------------------------------------------------------
__device__ __forceinline__ uint32_t smem_u32(const void* p) {
    uint32_t a;
    asm("{ .reg .u64 t; cvta.to.shared.u64 t, %1; cvt.u32.u64 %0, t; }" : "=r"(a) : "l"(p));
    return a;
}

#define CP_ASYNC16(dst, src) \
    asm volatile("cp.async.cg.shared.global [%0], [%1], 16;" :: "r"(dst), "l"(src))
#define CP_COMMIT() asm volatile("cp.async.commit_group;")
#define CP_WAIT(n)  asm volatile("cp.async.wait_group %0;" :: "n"(n))

__device__ __forceinline__ uint32_t swz(uint32_t off) { return off ^ ((off >> 3) & 0x70); }

__device__ __forceinline__ uint32_t f2tf32(float f) {
    uint32_t r;
    asm("cvt.rna.tf32.f32 %0, %1;" : "=r"(r) : "f"(f));
    return r;
}

// m16n8k8 tf32 mma, fp32 accumulate (sm_80+)
__device__ __forceinline__ void mma_tf32(float c[4],
                                         uint32_t a0, uint32_t a1, uint32_t a2, uint32_t a3,
                                         uint32_t b0, uint32_t b1) {
    asm volatile(
        "mma.sync.aligned.m16n8k8.row.col.f32.tf32.tf32.f32 "
        "{%0,%1,%2,%3}, {%4,%5,%6,%7}, {%8,%9}, {%0,%1,%2,%3};"
        : "+f"(c[0]), "+f"(c[1]), "+f"(c[2]), "+f"(c[3])
        : "r"(a0), "r"(a1), "r"(a2), "r"(a3), "r"(b0), "r"(b1));
}

// ---------------------------------------------------------------------------
// Weight transpose: out[c][r] = in[r][c], written into g_wT + dst_off
// ---------------------------------------------------------------------------
__global__ __launch_bounds__(256)
void transpose_k(const float* __restrict__ in, int dst_off, int R, int C)
{
    __shared__ float t[32][33];
    const int c0 = blockIdx.x * 32, r0 = blockIdx.y * 32;
    const int tx = threadIdx.x, ty = threadIdx.y;
#pragma unroll
    for (int i = ty; i < 32; i += 8)
        t[i][tx] = in[(r0 + i) * C + c0 + tx];
    __syncthreads();
#pragma unroll
    for (int i = ty; i < 32; i += 8)
        g_wT[dst_off + (c0 + i) * R + r0 + tx] = t[tx][i];
}

// ---------------------------------------------------------------------------
// tf32 mma.sync GEMM (unchanged from R4, passing)
// ---------------------------------------------------------------------------
#define TK          32
#define STAGES      3
#define STAGE_BYTES 32768                     // A 16KB + B 16KB
#define STAGE_F     8192
#define SMEM_GEMM   (STAGES * STAGE_BYTES)    // 98304

template <int MODE>
__device__ __forceinline__ void load_stage(const float* Ap, const float* Bt,
                                           uint32_t sb, int m0, int n0, int tid,
                                           int s, int k0)
{
    const uint32_t base = sb + s * STAGE_BYTES;
#pragma unroll
    for (int j = 0; j < 4; j++) {
        const int idx = tid + j * 256;
        const int r = idx >> 3, c = idx & 7;
        CP_ASYNC16(base + swz(r * 128 + c * 16), Ap + (m0 + r) * CDIM + k0 + c * 4);
    }
#pragma unroll
    for (int j = 0; j < 4; j++) {
        const int idx = tid + j * 256;
        const int r = idx >> 3, c = idx & 7;
        CP_ASYNC16(base + 16384 + swz(r * 128 + c * 16), Bt + (n0 + r) * CDIM + k0 + c * 4);
    }
}

template <int MODE>
__global__ __launch_bounds__(256, 2)
void tc_gemm(const float* __restrict__ A,
             int bt_off,
             const float* __restrict__ bias,
             const float* __restrict__ bQ,
             const float* __restrict__ bK,
             const float* __restrict__ bV,
             float* __restrict__ Cout)
{
    extern __shared__ float smemf[];
    const uint32_t sb = smem_u32(smemf);
    const int tid  = threadIdx.x;
    const int lane = tid & 31;
    const int wid  = tid >> 5;
    const int gid  = lane >> 2;
    const int tig  = lane & 3;
    const int wm   = (wid & 3) * 32;
    const int wn   = (wid >> 2) * 64;

    const int m0 = blockIdx.y * 128;
    const int n0 = blockIdx.x * 128;

    const float* Ap = (MODE == 1) ? (const float*)g_att : A;
    const float* Bt = g_wT + bt_off;

    float acc[2][8][4];
#pragma unroll
    for (int mt = 0; mt < 2; mt++)
#pragma unroll
        for (int nt = 0; nt < 8; nt++)
#pragma unroll
            for (int j = 0; j < 4; j++) acc[mt][nt][j] = 0.0f;

    load_stage<MODE>(Ap, Bt, sb, m0, n0, tid, 0, 0);
    CP_COMMIT();
    load_stage<MODE>(Ap, Bt, sb, m0, n0, tid, 1, TK);
    CP_COMMIT();

    const int NIT = CDIM / TK;
    const int xr  = gid << 2;

    int slot = 0;
    for (int i = 0; i < NIT; i++) {
        CP_WAIT(1);
        __syncthreads();

        if (i + 2 < NIT)
            load_stage<MODE>(Ap, Bt, sb, m0, n0, tid, (i + 2) % STAGES, (i + 2) * TK);
        CP_COMMIT();

        const float* As = smemf + slot * STAGE_F;
        const float* Bs = As + 4096;

#pragma unroll
        for (int ks = 0; ks < 4; ks++) {
            const int c0 = ((ks * 8) + tig) ^ xr;
            const int c4 = c0 ^ 4;

            uint32_t a[2][4];
#pragma unroll
            for (int mt = 0; mt < 2; mt++) {
                const int r0 = wm + mt * 16 + gid;
                const int r1 = r0 + 8;
                a[mt][0] = f2tf32(As[r0 * 32 + c0]);
                a[mt][1] = f2tf32(As[r1 * 32 + c0]);
                a[mt][2] = f2tf32(As[r0 * 32 + c4]);
                a[mt][3] = f2tf32(As[r1 * 32 + c4]);
            }
#pragma unroll
            for (int nt = 0; nt < 8; nt++) {
                const int n = wn + nt * 8 + gid;
                const uint32_t b0 = f2tf32(Bs[n * 32 + c0]);
                const uint32_t b1 = f2tf32(Bs[n * 32 + c4]);
                mma_tf32(acc[0][nt], a[0][0], a[0][1], a[0][2], a[0][3], b0, b1);
                mma_tf32(acc[1][nt], a[1][0], a[1][1], a[1][2], a[1][3], b0, b1);
            }
        }
        slot = (slot + 1) % STAGES;
    }

#pragma unroll
    for (int mt = 0; mt < 2; mt++) {
#pragma unroll
        for (int half = 0; half < 2; half++) {
            const int row = m0 + wm + mt * 16 + gid + half * 8;
#pragma unroll
            for (int nt = 0; nt < 8; nt++) {
                const int col = n0 + wn + nt * 8 + tig * 2;
                float v0 = acc[mt][nt][half * 2 + 0] + bias[col];
                float v1 = acc[mt][nt][half * 2 + 1] + bias[col + 1];

                if (MODE == 1) {
                    *(float2*)&Cout[(size_t)row * CDIM + col] = make_float2(v0, v1);
                } else {
                    const int sec = col >> 10;
                    const int n2  = col & 1023;
                    const float* hb = (sec == 0) ? bQ : (sec == 1) ? bK : bV;
                    v0 += hb[n2];
                    v1 += hb[n2 + 1];
                    const int h  = n2 >> 6, dd = n2 & 63;
                    const int b_ = row >> 11, t = row & (TLEN - 1);
                    float* base = (sec == 0) ? g_q : (sec == 1) ? g_k : g_v;
                    *(float2*)&base[(((size_t)(b_ * NHEAD + h) * TLEN) + t) * HDIM + dd] =
                        make_float2(v0, v1);
                }
            }
        }
    }
}

// ---------------------------------------------------------------------------
// Flash attention with split-tf32 mma (3xTF32). 64 q-rows/CTA, 4 warps.
// DELTA vs R5/R6: '#pragma unroll 2' on the two ks loops. The fully-unrolled
// version produced ~4-5k-instruction basic blocks; ptxas blowup is the prime
// suspect for the container timeout. Everything else is byte-identical.
// ---------------------------------------------------------------------------
#define FL_SMEM (17664 * 4)   // Qs 4352 + Ks 4352 + Vs 4608 + Ps 4352 floats

__global__ __launch_bounds__(128, 2)
void flash_mma()
{
    extern __shared__ float sm[];
    float* Qs = sm;            // [64][68]
    float* Ks = sm + 4352;     // [64][68]
    float* Vs = sm + 8704;     // [64][72]
    float* Ps = sm + 13312;    // [64][68]

    const int tid  = threadIdx.x;
    const int lane = tid & 31;
    const int wid  = tid >> 5;
    const int gid  = lane >> 2;
    const int tig  = lane & 3;
    const int wr0  = wid * 16;

    const int qt = (int)gridDim.x - 1 - (int)blockIdx.x;   // heavy tiles first
    const int h  = blockIdx.y;
    const int b  = blockIdx.z;
    const int bh = b * NHEAD + h;
    const int q0 = qt * 64;

    // Load Q tile (pre-scaled by 1/sqrt(d))
    for (int idx = tid; idx < 64 * 16; idx += 128) {
        const int row = idx >> 4, c = (idx & 15) * 4;
        float4 v = *(const float4*)(g_q + ((size_t)bh * TLEN + q0 + row) * HDIM + c);
        *(float4*)(Qs + row * 68 + c) =
            make_float4(v.x * 0.125f, v.y * 0.125f, v.z * 0.125f, v.w * 0.125f);
    }

    float o[8][4];
#pragma unroll
    for (int nt = 0; nt < 8; nt++)
#pragma unroll
        for (int j = 0; j < 4; j++) o[nt][j] = 0.0f;
    float mrow[2] = {-1e30f, -1e30f};
    float lrow[2] = {0.0f, 0.0f};

    for (int kt = 0; kt <= qt; kt++) {
        __syncthreads();   // previous iteration done with Ks/Vs
        for (int idx = tid; idx < 64 * 16; idx += 128) {
            const int row = idx >> 4, c = (idx & 15) * 4;
            const size_t src = ((size_t)bh * TLEN + kt * 64 + row) * HDIM + c;
            *(float4*)(Ks + row * 68 + c) = *(const float4*)(g_k + src);
            *(float4*)(Vs + row * 72 + c) = *(const float4*)(g_v + src);
        }
        __syncthreads();

        // ---- S = Q K^T (split tf32) ----
        float s[8][4];
#pragma unroll
        for (int nt = 0; nt < 8; nt++)
#pragma unroll
            for (int j = 0; j < 4; j++) s[nt][j] = 0.0f;

#pragma unroll 2
        for (int ks = 0; ks < 8; ks++) {
            const int kc = ks * 8 + tig;
            float af[4];
            af[0] = Qs[(wr0 + gid) * 68 + kc];
            af[1] = Qs[(wr0 + gid + 8) * 68 + kc];
            af[2] = Qs[(wr0 + gid) * 68 + kc + 4];
            af[3] = Qs[(wr0 + gid + 8) * 68 + kc + 4];
            uint32_t ah[4], al[4];
#pragma unroll
            for (int j = 0; j < 4; j++) {
                ah[j] = f2tf32(af[j]);
                al[j] = f2tf32(af[j] - __uint_as_float(ah[j]));
            }
#pragma unroll
            for (int nt = 0; nt < 8; nt++) {
                const float b0f = Ks[(nt * 8 + gid) * 68 + kc];
                const float b1f = Ks[(nt * 8 + gid) * 68 + kc + 4];
                const uint32_t bh0 = f2tf32(b0f);
                const uint32_t bh1 = f2tf32(b1f);
                const uint32_t bl0 = f2tf32(b0f - __uint_as_float(bh0));
                const uint32_t bl1 = f2tf32(b1f - __uint_as_float(bh1));
                mma_tf32(s[nt], ah[0], ah[1], ah[2], ah[3], bh0, bh1);
                mma_tf32(s[nt], ah[0], ah[1], ah[2], ah[3], bl0, bl1);
                mma_tf32(s[nt], al[0], al[1], al[2], al[3], bh0, bh1);
            }
        }

        // Causal mask (only the diagonal tile)
        if (kt == qt) {
#pragma unroll
            for (int nt = 0; nt < 8; nt++) {
#pragma unroll
                for (int j = 0; j < 4; j++) {
                    const int col = nt * 8 + 2 * tig + (j & 1);
                    const int row = wr0 + gid + (j >> 1) * 8;
                    if (col > row) s[nt][j] = -1e30f;
                }
            }
        }

        // Row max over tile (quad reduction)
        float tmax[2] = {-1e30f, -1e30f};
#pragma unroll
        for (int nt = 0; nt < 8; nt++) {
            tmax[0] = fmaxf(tmax[0], fmaxf(s[nt][0], s[nt][1]));
            tmax[1] = fmaxf(tmax[1], fmaxf(s[nt][2], s[nt][3]));
        }
#pragma unroll
        for (int d = 1; d <= 2; d <<= 1) {
            tmax[0] = fmaxf(tmax[0], __shfl_xor_sync(0xFFFFFFFFu, tmax[0], d));
            tmax[1] = fmaxf(tmax[1], __shfl_xor_sync(0xFFFFFFFFu, tmax[1], d));
        }
        const float mnew0 = fmaxf(mrow[0], tmax[0]);
        const float mnew1 = fmaxf(mrow[1], tmax[1]);
        const float corr0 = __expf(mrow[0] - mnew0);
        const float corr1 = __expf(mrow[1] - mnew1);

        // p = exp(s - m), row sums, stage P to SMEM
        float ps[2] = {0.0f, 0.0f};
#pragma unroll
        for (int nt = 0; nt < 8; nt++) {
            const float p0 = __expf(s[nt][0] - mnew0);
            const float p1 = __expf(s[nt][1] - mnew0);
            const float p2 = __expf(s[nt][2] - mnew1);
            const float p3 = __expf(s[nt][3] - mnew1);
            ps[0] += p0 + p1;
            ps[1] += p2 + p3;
            *(float2*)(Ps + (wr0 + gid) * 68 + nt * 8 + 2 * tig)     = make_float2(p0, p1);
            *(float2*)(Ps + (wr0 + gid + 8) * 68 + nt * 8 + 2 * tig) = make_float2(p2, p3);
        }
#pragma unroll
        for (int d = 1; d <= 2; d <<= 1) {
            ps[0] += __shfl_xor_sync(0xFFFFFFFFu, ps[0], d);
            ps[1] += __shfl_xor_sync(0xFFFFFFFFu, ps[1], d);
        }
        lrow[0] = lrow[0] * corr0 + ps[0];
        lrow[1] = lrow[1] * corr1 + ps[1];
#pragma unroll
        for (int nt = 0; nt < 8; nt++) {
            o[nt][0] *= corr0; o[nt][1] *= corr0;
            o[nt][2] *= corr1; o[nt][3] *= corr1;
        }
        mrow[0] = mnew0;
        mrow[1] = mnew1;
        __syncwarp();   // P rows of this warp visible to the whole warp

        // ---- O += P V (split tf32) ----
#pragma unroll 2
        for (int ks = 0; ks < 8; ks++) {
            const int kc = ks * 8 + tig;
            float af[4];
            af[0] = Ps[(wr0 + gid) * 68 + kc];
            af[1] = Ps[(wr0 + gid + 8) * 68 + kc];
            af[2] = Ps[(wr0 + gid) * 68 + kc + 4];
            af[3] = Ps[(wr0 + gid + 8) * 68 + kc + 4];
            uint32_t ah[4], al[4];
#pragma unroll
            for (int j = 0; j < 4; j++) {
                ah[j] = f2tf32(af[j]);
                al[j] = f2tf32(af[j] - __uint_as_float(ah[j]));
            }
#pragma unroll
            for (int nt = 0; nt < 8; nt++) {
                const float b0f = Vs[kc * 72 + nt * 8 + gid];
                const float b1f = Vs[(kc + 4) * 72 + nt * 8 + gid];
                const uint32_t bh0 = f2tf32(b0f);
                const uint32_t bh1 = f2tf32(b1f);
                const uint32_t bl0 = f2tf32(b0f - __uint_as_float(bh0));
                const uint32_t bl1 = f2tf32(b1f - __uint_as_float(bh1));
                mma_tf32(o[nt], ah[0], ah[1], ah[2], ah[3], bh0, bh1);
                mma_tf32(o[nt], ah[0], ah[1], ah[2], ah[3], bl0, bl1);
                mma_tf32(o[nt], al[0], al[1], al[2], al[3], bh0, bh1);
            }
        }
    }

    // Epilogue: divide by l, write to g_att [b,t, h*64+d]
    const float inv0 = 1.0f / lrow[0];
    const float inv1 = 1.0f / lrow[1];
    const size_t r0 = (size_t)b * TLEN + q0 + wr0 + gid;
#pragma unroll
    for (int nt = 0; nt < 8; nt++) {
        const int col = h * HDIM + nt * 8 + 2 * tig;
        *(float2*)(g_att + r0 * CDIM + col) =
            make_float2(o[nt][0] * inv0, o[nt][1] * inv0);
        *(float2*)(g_att + (r0 + 8) * CDIM + col) =
            make_float2(o[nt][2] * inv1, o[nt][3] * inv1);
    }
}

// ---------------------------------------------------------------------------
// kernel_launch
// Inputs: 0:x 1:W_attn 2:b_attn 3:W_proj 4:b_proj 5:bQ 6:bK 7:bV
// ---------------------------------------------------------------------------
extern "C" void kernel_launch(void* const* d_in, const int* in_sizes, int n_in,
                              void* d_out, int out_size)
{
    const float* x      = (const float*)d_in[0];
    const float* W_attn = (const float*)d_in[1];
    const float* b_attn = (const float*)d_in[2];
    const float* W_proj = (const float*)d_in[3];
    const float* b_proj = (const float*)d_in[4];
    const float* bQ     = (const float*)d_in[5];
    const float* bK     = (const float*)d_in[6];
    const float* bV     = (const float*)d_in[7];
    float* out = (float*)d_out;

    cudaFuncSetAttribute(tc_gemm<0>, cudaFuncAttributeMaxDynamicSharedMemorySize, SMEM_GEMM);
    cudaFuncSetAttribute(tc_gemm<1>, cudaFuncAttributeMaxDynamicSharedMemorySize, SMEM_GEMM);
    cudaFuncSetAttribute(flash_mma, cudaFuncAttributeMaxDynamicSharedMemorySize, FL_SMEM);

    // 0) Transpose weights into K-major form
    {
        dim3 tb(32, 8);
        transpose_k<<<dim3(3 * CDIM / 32, CDIM / 32), tb>>>(W_attn, 0, CDIM, 3 * CDIM);
        transpose_k<<<dim3(CDIM / 32, CDIM / 32), tb>>>(W_proj, WT_PROJ_OFF, CDIM, CDIM);
    }

    // 1) QKV GEMM (tf32 mma.sync) + bias + head scatter
    {
        dim3 grid(3 * CDIM / 128, MTOT / 128);   // (24, 64)
        tc_gemm<0><<<grid, 256, SMEM_GEMM>>>(x, 0, b_attn, bQ, bK, bV, nullptr);
    }

    // 2) Causal flash attention (split-tf32 mma)
    {
        dim3 grid(TLEN / 64, NHEAD, BSZ);        // (32, 16, 4)
        flash_mma<<<grid, 128, FL_SMEM>>>();
    }

    // 3) Projection GEMM (tf32 mma.sync) + b_proj
    {
        dim3 grid(CDIM / 128, MTOT / 128);       // (8, 64)
        tc_gemm<1><<<grid, 256, SMEM_GEMM>>>(nullptr, WT_PROJ_OFF, b_proj,
                                             nullptr, nullptr, nullptr, out);
    }
}